// round 13
// baseline (speedup 1.0000x reference)
#include <cuda_runtime.h>
#include <cstdint>

// YOLO post-process: (16, 25200, 85) fp32 -> (16, 25200, 6) fp32
//
// R12: R7 geometry (128-row/43520B tiles, depth-2 cp.async.bulk, 2 blocks/SM,
//      static contiguous quad-aligned chunks) with the block-wide barrier
//      removed from the steady-state loop: producer/consumer mbarrier ring.
//      full[slot] (count=1) <- TMA complete_tx; empty[slot] (count=4) <- one
//      arrive per consumer warp after its reads. Warps slip independently;
//      outputs stored directly (warp rows contiguous -> full sectors).

#define N_ROWS        403200          // 16 * 25200
#define N_CH          85
#define N_OUT         6
#define CONF_TH       0.25f
#define TILE_ROWS     128
#define BLOCK_THREADS 128
#define TILE_FLOATS   (TILE_ROWS * N_CH)     // 10880
#define TILE_BYTES    (TILE_FLOATS * 4)      // 43520
#define GRID_BLOCKS   296                    // 2 per SM * 148

// Chunking in quad-rows (4 rows = 1360 B -> bulk-copy sources 16B-aligned):
//   total quads = 100800 = 296*340 + 160 -> first 160 blocks get 341 quads.
#define QUADS_BASE    340
#define QUADS_EXTRA   160

// dynamic smem: [0,16) full mbar[2], [16,32) empty mbar[2], [32,+2T) in bufs
#define SM_IN    32
#define SM_TOTAL (SM_IN + 2 * TILE_BYTES)            // 87072

__device__ __forceinline__ unsigned smem_u32(const void* p) {
    unsigned a;
    asm("{ .reg .u64 t; cvta.to.shared.u64 t, %1; cvt.u32.u64 %0, t; }"
        : "=r"(a) : "l"(p));
    return a;
}

__device__ __forceinline__ void mbar_init(unsigned addr, unsigned count) {
    asm volatile("mbarrier.init.shared.b64 [%0], %1;" :: "r"(addr), "r"(count) : "memory");
}

__device__ __forceinline__ void mbar_arrive(unsigned addr) {
    asm volatile("mbarrier.arrive.release.cta.shared::cta.b64 _, [%0];"
                 :: "r"(addr) : "memory");
}

__device__ __forceinline__ void bulk_load(unsigned dst_smem, const void* gsrc,
                                          unsigned bytes, unsigned mbar) {
    asm volatile("mbarrier.arrive.expect_tx.shared.b64 _, [%0], %1;"
                 :: "r"(mbar), "r"(bytes) : "memory");
    asm volatile("cp.async.bulk.shared::cta.global.mbarrier::complete_tx::bytes "
                 "[%0], [%1], %2, [%3];"
                 :: "r"(dst_smem), "l"(gsrc), "r"(bytes), "r"(mbar) : "memory");
}

__device__ __forceinline__ void mbar_wait(unsigned addr, unsigned parity) {
    asm volatile(
        "{\n\t"
        ".reg .pred P;\n\t"
        "W%=:\n\t"
        "mbarrier.try_wait.parity.acquire.cta.shared::cta.b64 P, [%0], %1, 0x989680;\n\t"
        "@P bra D%=;\n\t"
        "bra W%=;\n\t"
        "D%=:\n\t"
        "}"
        :: "r"(addr), "r"(parity) : "memory");
}

__global__ __launch_bounds__(BLOCK_THREADS, 2)
void yolo_post_kernel(const float* __restrict__ in, float2* __restrict__ out2)
{
    extern __shared__ char sb[];
    const unsigned base = smem_u32(sb);
    float* const in_base = reinterpret_cast<float*>(sb + SM_IN);

    const int tid  = threadIdx.x;
    const int lane = tid & 31;
    const int b    = blockIdx.x;

    // full[s] at base + s*8 ; empty[s] at base + 16 + s*8
    const unsigned FULL0  = base + 0;
    const unsigned EMPTY0 = base + 16;

    // Contiguous chunk (quad-row granularity).
    const int q_start = QUADS_BASE * b + (b < QUADS_EXTRA ? b : QUADS_EXTRA);
    const int row0    = 4 * q_start;
    const int n_rows  = 4 * (QUADS_BASE + (b < QUADS_EXTRA ? 1 : 0));   // 1364 or 1360
    const int n_tiles = (n_rows + TILE_ROWS - 1) / TILE_ROWS;           // 11

    if (tid == 0) {
        mbar_init(FULL0 + 0, 1);
        mbar_init(FULL0 + 8, 1);
        mbar_init(EMPTY0 + 0, 4);   // one arrive per consumer warp
        mbar_init(EMPTY0 + 8, 4);
    }
    __syncthreads();   // only block-wide barrier: after init, before first TMA

    // Prologue: issue tile 0 into slot 0 (empty[0] fresh, no wait needed).
    if (tid == 0) {
        int tr0 = (n_rows < TILE_ROWS) ? n_rows : TILE_ROWS;
        bulk_load(base + SM_IN, in + (size_t)row0 * N_CH,
                  (unsigned)(tr0 * N_CH * 4), FULL0 + 0);
    }

    for (int it = 0; it < n_tiles; ++it) {
        const int slot = it & 1;

        // ---- producer (tid 0): issue tile it+1 into the other slot ----
        if (tid == 0 && it + 1 < n_tiles) {
            const int t_n    = it + 1;
            const int slot_w = t_n & 1;
            const int g      = t_n >> 1;               // generation of slot_w
            // Wait consumers done with generation g-1 of this slot.
            // parity (g+1)&1: fresh-barrier first wait (g==0) passes.
            mbar_wait(EMPTY0 + slot_w * 8, (unsigned)((g + 1) & 1));
            const int r_off = t_n * TILE_ROWS;
            int tr = n_rows - r_off;
            if (tr > TILE_ROWS) tr = TILE_ROWS;
            bulk_load(base + SM_IN + slot_w * TILE_BYTES,
                      in + (size_t)(row0 + r_off) * N_CH,
                      (unsigned)(tr * N_CH * 4), FULL0 + slot_w * 8);
        }

        // ---- consumers: wait tile, compute own row, store, release slot ----
        mbar_wait(FULL0 + slot * 8, (unsigned)((it >> 1) & 1));

        const int r_off = it * TILE_ROWS;
        int tile_rows = n_rows - r_off;
        if (tile_rows > TILE_ROWS) tile_rows = TILE_ROWS;

        if (tid < tile_rows) {
            const float* row = in_base + slot * TILE_FLOATS + tid * N_CH;

            const float x    = row[0];
            const float y    = row[1];
            const float w    = row[2];
            const float h    = row[3];
            const float conf = row[4];

            float b0 = row[5 +  0], b1 = row[5 + 20], b2 = row[5 + 40], b3 = row[5 + 60];
            int   i0 = 0,           i1 = 20,          i2 = 40,          i3 = 60;

            #pragma unroll
            for (int c = 1; c < 20; c++) {
                float v0 = row[5 +  0 + c];
                float v1 = row[5 + 20 + c];
                float v2 = row[5 + 40 + c];
                float v3 = row[5 + 60 + c];
                if (v0 > b0) { b0 = v0; i0 =  0 + c; }
                if (v1 > b1) { b1 = v1; i1 = 20 + c; }
                if (v2 > b2) { b2 = v2; i2 = 40 + c; }
                if (v3 > b3) { b3 = v3; i3 = 60 + c; }
            }
            // Ordered merge: ties keep the earlier quarter -> first-index semantics.
            if (b1 > b0) { b0 = b1; i0 = i1; }
            if (b2 > b0) { b0 = b2; i0 = i2; }
            if (b3 > b0) { b0 = b3; i0 = i3; }

            const float score = conf * b0;
            const bool  pass  = score > CONF_TH;
            const float hw = 0.5f * w;
            const float hh = 0.5f * h;

            float o0 = 0.f, o1 = 0.f, o2 = 0.f, o3 = 0.f, o4 = 0.f, o5 = 0.f;
            if (pass) {
                o0 = x - hw;
                o1 = y - hh;
                o2 = x + hw;
                o3 = y + hh;
                o4 = score;
                o5 = (float)i0;
            }

            // Direct store: warp rows contiguous -> 768B fully-covered region.
            float2* dst = out2 + (size_t)(row0 + r_off + tid) * 3;
            dst[0] = make_float2(o0, o1);
            dst[1] = make_float2(o2, o3);
            dst[2] = make_float2(o4, o5);
        }

        // Release the slot: one arrive per warp after all its lanes read.
        __syncwarp();
        if (lane == 0) mbar_arrive(EMPTY0 + slot * 8);
    }
}

extern "C" void kernel_launch(void* const* d_in, const int* in_sizes, int n_in,
                              void* d_out, int out_size)
{
    const float* in  = (const float*)d_in[0];
    float2*      out = (float2*)d_out;
    cudaFuncSetAttribute(yolo_post_kernel,
                         cudaFuncAttributeMaxDynamicSharedMemorySize, SM_TOTAL);
    yolo_post_kernel<<<GRID_BLOCKS, BLOCK_THREADS, SM_TOTAL>>>(in, out);
}

// round 14
// speedup vs baseline: 1.0565x; 1.0565x over previous
#include <cuda_runtime.h>
#include <cstdint>

// YOLO post-process: (16, 25200, 85) fp32 -> (16, 25200, 6) fp32
//
// R13: R7 geometry (128-row/43520B tiles, depth-2, 2 blocks/SM, static
//      contiguous quad-aligned chunks) with DUAL-PATH tile loads:
//        rows 0..95   (32640B) via cp.async.bulk   (TMA engine)
//        rows 96..127 (10880B) via cp.async.cg 16B (LSU path, all threads)
//      The two paths run concurrently per SM, bypassing the per-SM TMA
//      engine service-rate limit. One barrier per iteration, direct stores.

#define N_ROWS        403200          // 16 * 25200
#define N_CH          85
#define N_OUT         6
#define CONF_TH       0.25f
#define TILE_ROWS     128
#define TMA_ROWS      96
#define BLOCK_THREADS 128
#define TILE_FLOATS   (TILE_ROWS * N_CH)     // 10880
#define TILE_BYTES    (TILE_FLOATS * 4)      // 43520
#define TMA_BYTES     (TMA_ROWS * N_CH * 4)  // 32640
#define LDG_OFF_B     TMA_BYTES              // byte offset of LDG region in tile
#define LDG_VEC4      ((TILE_BYTES - TMA_BYTES) / 16)   // 680
#define GRID_BLOCKS   296                    // 2 per SM * 148

// Chunking in quad-rows (4 rows = 1360 B -> all sources 16B-aligned):
//   total quads = 100800 = 296*340 + 160 -> first 160 blocks get 341 quads.
#define QUADS_BASE    340
#define QUADS_EXTRA   160

// dynamic smem: [0,16) full mbar[2], [32,+2T) in bufs
#define SM_IN    32
#define SM_TOTAL (SM_IN + 2 * TILE_BYTES)            // 87072

__device__ __forceinline__ unsigned smem_u32(const void* p) {
    unsigned a;
    asm("{ .reg .u64 t; cvta.to.shared.u64 t, %1; cvt.u32.u64 %0, t; }"
        : "=r"(a) : "l"(p));
    return a;
}

__device__ __forceinline__ void mbar_init(unsigned addr, unsigned count) {
    asm volatile("mbarrier.init.shared.b64 [%0], %1;" :: "r"(addr), "r"(count) : "memory");
}

__device__ __forceinline__ void bulk_load(unsigned dst_smem, const void* gsrc,
                                          unsigned bytes, unsigned mbar) {
    asm volatile("mbarrier.arrive.expect_tx.shared.b64 _, [%0], %1;"
                 :: "r"(mbar), "r"(bytes) : "memory");
    asm volatile("cp.async.bulk.shared::cta.global.mbarrier::complete_tx::bytes "
                 "[%0], [%1], %2, [%3];"
                 :: "r"(dst_smem), "l"(gsrc), "r"(bytes), "r"(mbar) : "memory");
}

__device__ __forceinline__ void mbar_wait(unsigned addr, unsigned parity) {
    asm volatile(
        "{\n\t"
        ".reg .pred P;\n\t"
        "W%=:\n\t"
        "mbarrier.try_wait.parity.acquire.cta.shared::cta.b64 P, [%0], %1, 0x989680;\n\t"
        "@P bra D%=;\n\t"
        "bra W%=;\n\t"
        "D%=:\n\t"
        "}"
        :: "r"(addr), "r"(parity) : "memory");
}

__device__ __forceinline__ void cp_async16(unsigned dst, const void* src) {
    asm volatile("cp.async.cg.shared.global [%0], [%1], 16;"
                 :: "r"(dst), "l"(src) : "memory");
}

#define CP_COMMIT() asm volatile("cp.async.commit_group;" ::: "memory")
#define CP_WAIT0()  asm volatile("cp.async.wait_group 0;" ::: "memory")

__global__ __launch_bounds__(BLOCK_THREADS, 2)
void yolo_post_kernel(const float* __restrict__ in, float2* __restrict__ out2)
{
    extern __shared__ char sb[];
    const unsigned base = smem_u32(sb);
    float* const in_base = reinterpret_cast<float*>(sb + SM_IN);
    const char* const inb = reinterpret_cast<const char*>(in);

    const int tid = threadIdx.x;
    const int b   = blockIdx.x;

    // Contiguous chunk (quad-row granularity).
    const int q_start = QUADS_BASE * b + (b < QUADS_EXTRA ? b : QUADS_EXTRA);
    const int row0    = 4 * q_start;
    const int n_rows  = 4 * (QUADS_BASE + (b < QUADS_EXTRA ? 1 : 0));   // 1364 or 1360
    const int n_tiles = (n_rows + TILE_ROWS - 1) / TILE_ROWS;           // 11

    if (tid == 0) {
        mbar_init(base + 0, 1);
        mbar_init(base + 8, 1);
    }
    __syncthreads();

    // Prologue: issue tile 0 into slot 0 (TMA portion + LDG portion).
    {
        int tr0 = (n_rows < TILE_ROWS) ? n_rows : TILE_ROWS;
        int trm = (tr0 < TMA_ROWS) ? tr0 : TMA_ROWS;
        if (tid == 0) {
            bulk_load(base + SM_IN, inb + (size_t)row0 * (N_CH * 4),
                      (unsigned)(trm * N_CH * 4), base + 0);
        }
        if (tr0 == TILE_ROWS) {
            const size_t gsrc = (size_t)(row0 + TMA_ROWS) * (N_CH * 4);
            #pragma unroll
            for (int i = tid; i < LDG_VEC4; i += BLOCK_THREADS)
                cp_async16(base + SM_IN + LDG_OFF_B + i * 16, inb + gsrc + i * 16);
            CP_COMMIT();
        }
    }

    for (int it = 0; it < n_tiles; ++it) {
        const int slot = it & 1;

        // Wait tile it: TMA portion via mbarrier, LDG portion via wait_group.
        mbar_wait(base + slot * 8, (unsigned)((it >> 1) & 1));
        CP_WAIT0();
        __syncthreads();   // cp.async data cross-thread visible; also fences
                           // slot_w consumers (iter it-1) before re-issue below

        // Issue tile it+1 into the other slot.
        const int t_n = it + 1;
        if (t_n < n_tiles) {
            const int slot_w = t_n & 1;
            const int r_b    = row0 + t_n * TILE_ROWS;
            int tr = n_rows - t_n * TILE_ROWS;
            if (tr > TILE_ROWS) tr = TILE_ROWS;
            int trm = (tr < TMA_ROWS) ? tr : TMA_ROWS;
            if (tid == 0) {
                bulk_load(base + SM_IN + slot_w * TILE_BYTES,
                          inb + (size_t)r_b * (N_CH * 4),
                          (unsigned)(trm * N_CH * 4), base + slot_w * 8);
            }
            if (tr == TILE_ROWS) {
                const size_t gsrc = (size_t)(r_b + TMA_ROWS) * (N_CH * 4);
                const unsigned dst0 = base + SM_IN + slot_w * TILE_BYTES + LDG_OFF_B;
                #pragma unroll
                for (int i = tid; i < LDG_VEC4; i += BLOCK_THREADS)
                    cp_async16(dst0 + i * 16, inb + gsrc + i * 16);
                CP_COMMIT();
            }
        }

        // ---- compute tile it: thread-per-row, direct stores ----
        const int r_off = it * TILE_ROWS;
        int tile_rows = n_rows - r_off;
        if (tile_rows > TILE_ROWS) tile_rows = TILE_ROWS;

        if (tid < tile_rows) {
            const float* row = in_base + slot * TILE_FLOATS + tid * N_CH;

            const float x    = row[0];
            const float y    = row[1];
            const float w    = row[2];
            const float h    = row[3];
            const float conf = row[4];

            float b0 = row[5 +  0], b1 = row[5 + 20], b2 = row[5 + 40], b3 = row[5 + 60];
            int   i0 = 0,           i1 = 20,          i2 = 40,          i3 = 60;

            #pragma unroll
            for (int c = 1; c < 20; c++) {
                float v0 = row[5 +  0 + c];
                float v1 = row[5 + 20 + c];
                float v2 = row[5 + 40 + c];
                float v3 = row[5 + 60 + c];
                if (v0 > b0) { b0 = v0; i0 =  0 + c; }
                if (v1 > b1) { b1 = v1; i1 = 20 + c; }
                if (v2 > b2) { b2 = v2; i2 = 40 + c; }
                if (v3 > b3) { b3 = v3; i3 = 60 + c; }
            }
            // Ordered merge: ties keep the earlier quarter -> first-index.
            if (b1 > b0) { b0 = b1; i0 = i1; }
            if (b2 > b0) { b0 = b2; i0 = i2; }
            if (b3 > b0) { b0 = b3; i0 = i3; }

            const float score = conf * b0;
            const bool  pass  = score > CONF_TH;
            const float hw = 0.5f * w;
            const float hh = 0.5f * h;

            float o0 = 0.f, o1 = 0.f, o2 = 0.f, o3 = 0.f, o4 = 0.f, o5 = 0.f;
            if (pass) {
                o0 = x - hw;
                o1 = y - hh;
                o2 = x + hw;
                o3 = y + hh;
                o4 = score;
                o5 = (float)i0;
            }

            // Direct store: warp rows contiguous -> fully covered 768B region.
            float2* dst = out2 + (size_t)(row0 + r_off + tid) * 3;
            dst[0] = make_float2(o0, o1);
            dst[1] = make_float2(o2, o3);
            dst[2] = make_float2(o4, o5);
        }
        // Slot-reuse safety: next re-issue of this slot happens after the
        // __syncthreads at the top of iteration it+1, which no thread passes
        // until every thread has finished this compute.
    }
}

extern "C" void kernel_launch(void* const* d_in, const int* in_sizes, int n_in,
                              void* d_out, int out_size)
{
    const float* in  = (const float*)d_in[0];
    float2*      out = (float2*)d_out;
    cudaFuncSetAttribute(yolo_post_kernel,
                         cudaFuncAttributeMaxDynamicSharedMemorySize, SM_TOTAL);
    yolo_post_kernel<<<GRID_BLOCKS, BLOCK_THREADS, SM_TOTAL>>>(in, out);
}